// round 2
// baseline (speedup 1.0000x reference)
#include <cuda_runtime.h>
#include <cuda_bf16.h>

// Problem constants (fixed by reference setup_inputs)
#define B_DIM 32
#define HW (1024 * 1024)
#define VEC (HW / 4)          // float4 pixels per image
#define THREADS 256
#define NBLOCKS (VEC / THREADS)
#define LAMBDA_F 0.1f

// Global accumulators: [0]=diff2, [1]=G2, [2]=H2. Zero-initialized at module
// load; the finalizing block resets them to zero each run, so every graph
// replay starts clean.
__device__ double g_acc[3];
__device__ unsigned int g_done_count;

__global__ __launch_bounds__(THREADS) void pra_fused_kernel(
    const float4* __restrict__ est, const float4* __restrict__ gt,
    float* __restrict__ out)
{
    int p = blockIdx.x * THREADS + threadIdx.x;   // vec-pixel index, p < VEC

    float4 se = make_float4(0.f, 0.f, 0.f, 0.f);  // per-pixel batch sum of est
    float4 sg = make_float4(0.f, 0.f, 0.f, 0.f);  // per-pixel batch sum of gt
    float4 e2 = make_float4(0.f, 0.f, 0.f, 0.f);  // per-pixel sum of est^2
    float diff2 = 0.f;

    #pragma unroll 8
    for (int b = 0; b < B_DIM; b++) {
        float4 e = __ldcs(&est[(size_t)b * VEC + p]);   // streaming: read-once data
        float4 g = __ldcs(&gt [(size_t)b * VEC + p]);
        se.x += e.x; se.y += e.y; se.z += e.z; se.w += e.w;
        sg.x += g.x; sg.y += g.y; sg.z += g.z; sg.w += g.w;
        e2.x = fmaf(e.x, e.x, e2.x);
        e2.y = fmaf(e.y, e.y, e2.y);
        e2.z = fmaf(e.z, e.z, e2.z);
        e2.w = fmaf(e.w, e.w, e2.w);
        float dx = e.x - g.x, dy = e.y - g.y, dz = e.z - g.z, dw = e.w - g.w;
        diff2 = fmaf(dx, dx, diff2);
        diff2 = fmaf(dy, dy, diff2);
        diff2 = fmaf(dz, dz, diff2);
        diff2 = fmaf(dw, dw, diff2);
    }

    float g2 = e2.x + e2.y + e2.z + e2.w;
    float h2 = (se.x > sg.x ? e2.x : 0.f)
             + (se.y > sg.y ? e2.y : 0.f)
             + (se.z > sg.z ? e2.z : 0.f)
             + (se.w > sg.w ? e2.w : 0.f);

    // ---- block reduction: warp shuffle then shared ----
    #pragma unroll
    for (int off = 16; off > 0; off >>= 1) {
        diff2 += __shfl_down_sync(0xffffffffu, diff2, off);
        g2    += __shfl_down_sync(0xffffffffu, g2,    off);
        h2    += __shfl_down_sync(0xffffffffu, h2,    off);
    }

    __shared__ float s_d[THREADS / 32];
    __shared__ float s_g[THREADS / 32];
    __shared__ float s_h[THREADS / 32];
    int lane = threadIdx.x & 31;
    int wid  = threadIdx.x >> 5;
    if (lane == 0) { s_d[wid] = diff2; s_g[wid] = g2; s_h[wid] = h2; }
    __syncthreads();

    if (wid == 0) {
        float d  = (lane < THREADS / 32) ? s_d[lane] : 0.f;
        float gg = (lane < THREADS / 32) ? s_g[lane] : 0.f;
        float hh = (lane < THREADS / 32) ? s_h[lane] : 0.f;
        #pragma unroll
        for (int off = 4; off > 0; off >>= 1) {
            d  += __shfl_down_sync(0xffffffffu, d,  off);
            gg += __shfl_down_sync(0xffffffffu, gg, off);
            hh += __shfl_down_sync(0xffffffffu, hh, off);
        }
        if (lane == 0) {
            atomicAdd(&g_acc[0], (double)d);
            atomicAdd(&g_acc[1], (double)gg);
            atomicAdd(&g_acc[2], (double)hh);
            __threadfence();
            unsigned int prev = atomicAdd(&g_done_count, 1u);
            if (prev == NBLOCKS - 1) {
                // Last block: all adds are globally visible. Read via atomics
                // (L2 path) to avoid any stale L1 view, finalize, and reset
                // state for the next graph replay.
                double diff2_t = atomicAdd(&g_acc[0], 0.0);
                double g2_t    = atomicAdd(&g_acc[1], 0.0);
                double h2_t    = atomicAdd(&g_acc[2], 0.0);
                out[0] = (float)(diff2_t / g2_t + (double)LAMBDA_F * (diff2_t / h2_t));
                g_acc[0] = 0.0;
                g_acc[1] = 0.0;
                g_acc[2] = 0.0;
                __threadfence();
                g_done_count = 0u;
            }
        }
    }
}

extern "C" void kernel_launch(void* const* d_in, const int* in_sizes, int n_in,
                              void* d_out, int out_size) {
    const float4* est = (const float4*)d_in[0];
    const float4* gt  = (const float4*)d_in[1];
    float* out = (float*)d_out;

    pra_fused_kernel<<<NBLOCKS, THREADS>>>(est, gt, out);
}

// round 3
// speedup vs baseline: 1.0587x; 1.0587x over previous
#include <cuda_runtime.h>
#include <cuda_bf16.h>

// Problem constants (fixed by reference setup_inputs)
#define B_DIM 32
#define HW (1024 * 1024)
#define VEC (HW / 4)          // float4 pixels per image
#define THREADS 128
#define NBLOCKS (VEC / THREADS)   // 2048
#define LAMBDA_F 0.1f

// Global accumulators: [0]=diff2, [1]=G2, [2]=H2. Zero-initialized at module
// load; the finalizing block resets them, so each graph replay starts clean.
__device__ double g_acc[3];
__device__ unsigned int g_done_count;

__global__ __launch_bounds__(THREADS) void pra_fused_kernel(
    const float4* __restrict__ est, const float4* __restrict__ gt,
    float* __restrict__ out)
{
    int p = blockIdx.x * THREADS + threadIdx.x;   // vec-pixel index, p < VEC

    // Per-pixel (x4 lanes) accumulators over the batch dimension:
    //   sd = sum_b (e - g)      (mask test: sum_b e > sum_b g  <=>  sd > 0)
    //   e2 = sum_b e^2
    float4 sd = make_float4(0.f, 0.f, 0.f, 0.f);
    float4 e2 = make_float4(0.f, 0.f, 0.f, 0.f);
    float diff2 = 0.f;

    #pragma unroll 8
    for (int b = 0; b < B_DIM; b++) {
        float4 e = est[(size_t)b * VEC + p];
        float4 g = gt [(size_t)b * VEC + p];
        float dx = e.x - g.x, dy = e.y - g.y, dz = e.z - g.z, dw = e.w - g.w;
        sd.x += dx; sd.y += dy; sd.z += dz; sd.w += dw;
        e2.x = fmaf(e.x, e.x, e2.x);
        e2.y = fmaf(e.y, e.y, e2.y);
        e2.z = fmaf(e.z, e.z, e2.z);
        e2.w = fmaf(e.w, e.w, e2.w);
        diff2 = fmaf(dx, dx, diff2);
        diff2 = fmaf(dy, dy, diff2);
        diff2 = fmaf(dz, dz, diff2);
        diff2 = fmaf(dw, dw, diff2);
    }

    float g2 = e2.x + e2.y + e2.z + e2.w;
    float h2 = (sd.x > 0.f ? e2.x : 0.f)
             + (sd.y > 0.f ? e2.y : 0.f)
             + (sd.z > 0.f ? e2.z : 0.f)
             + (sd.w > 0.f ? e2.w : 0.f);

    // ---- block reduction: warp shuffle then shared ----
    #pragma unroll
    for (int off = 16; off > 0; off >>= 1) {
        diff2 += __shfl_down_sync(0xffffffffu, diff2, off);
        g2    += __shfl_down_sync(0xffffffffu, g2,    off);
        h2    += __shfl_down_sync(0xffffffffu, h2,    off);
    }

    __shared__ float s_d[THREADS / 32];
    __shared__ float s_g[THREADS / 32];
    __shared__ float s_h[THREADS / 32];
    int lane = threadIdx.x & 31;
    int wid  = threadIdx.x >> 5;
    if (lane == 0) { s_d[wid] = diff2; s_g[wid] = g2; s_h[wid] = h2; }
    __syncthreads();

    if (wid == 0) {
        float d  = (lane < THREADS / 32) ? s_d[lane] : 0.f;
        float gg = (lane < THREADS / 32) ? s_g[lane] : 0.f;
        float hh = (lane < THREADS / 32) ? s_h[lane] : 0.f;
        #pragma unroll
        for (int off = 2; off > 0; off >>= 1) {
            d  += __shfl_down_sync(0xffffffffu, d,  off);
            gg += __shfl_down_sync(0xffffffffu, gg, off);
            hh += __shfl_down_sync(0xffffffffu, hh, off);
        }
        if (lane == 0) {
            atomicAdd(&g_acc[0], (double)d);
            atomicAdd(&g_acc[1], (double)gg);
            atomicAdd(&g_acc[2], (double)hh);
            __threadfence();
            unsigned int prev = atomicAdd(&g_done_count, 1u);
            if (prev == NBLOCKS - 1) {
                // Last block: all adds globally visible. Read via atomic path
                // (L2) to avoid stale L1, finalize, reset for next replay.
                double diff2_t = atomicAdd(&g_acc[0], 0.0);
                double g2_t    = atomicAdd(&g_acc[1], 0.0);
                double h2_t    = atomicAdd(&g_acc[2], 0.0);
                out[0] = (float)(diff2_t / g2_t + (double)LAMBDA_F * (diff2_t / h2_t));
                g_acc[0] = 0.0;
                g_acc[1] = 0.0;
                g_acc[2] = 0.0;
                __threadfence();
                g_done_count = 0u;
            }
        }
    }
}

extern "C" void kernel_launch(void* const* d_in, const int* in_sizes, int n_in,
                              void* d_out, int out_size) {
    const float4* est = (const float4*)d_in[0];
    const float4* gt  = (const float4*)d_in[1];
    float* out = (float*)d_out;

    pra_fused_kernel<<<NBLOCKS, THREADS>>>(est, gt, out);
}

// round 4
// speedup vs baseline: 1.1508x; 1.0870x over previous
#include <cuda_runtime.h>
#include <cstdint>

// Problem constants (fixed by reference setup_inputs)
#define B_DIM 32
#define HW (1024 * 1024)
#define VEC (HW / 4)              // float4 pixels per image = 262144
#define TPB 256
#define F4B 256                   // float4 pixels per block tile
#define NBLOCKS (VEC / F4B)       // 1024 blocks -> single resident wave
#define STAGES 4
#define TILE_BYTES (F4B * 16)     // 4096 bytes per array per stage
#define LAMBDA_F 0.1f

// Global accumulators: [0]=diff2, [1]=G2, [2]=H2. Zero-init at load; the
// finalizing block resets them so every graph replay starts clean.
__device__ double g_acc[3];
__device__ unsigned int g_done_count;

__device__ __forceinline__ void bulk_ld(unsigned dst_smem, const void* src,
                                        unsigned bytes, unsigned mbar) {
    asm volatile(
        "cp.async.bulk.shared::cta.global.mbarrier::complete_tx::bytes "
        "[%0], [%1], %2, [%3];"
        :: "r"(dst_smem), "l"(src), "r"(bytes), "r"(mbar) : "memory");
}

__device__ __forceinline__ void mbar_expect_tx(unsigned mbar, unsigned bytes) {
    asm volatile("mbarrier.arrive.expect_tx.shared.b64 _, [%0], %1;"
                 :: "r"(mbar), "r"(bytes) : "memory");
}

__device__ __forceinline__ void mbar_wait_parity(unsigned mbar, unsigned parity) {
    asm volatile(
        "{\n\t"
        ".reg .pred P;\n\t"
        "WAIT_%=:\n\t"
        "mbarrier.try_wait.parity.acquire.cta.shared::cta.b64 P, [%0], %1, 0x989680;\n\t"
        "@P bra.uni DONE_%=;\n\t"
        "bra.uni WAIT_%=;\n\t"
        "DONE_%=:\n\t"
        "}"
        :: "r"(mbar), "r"(parity) : "memory");
}

__global__ __launch_bounds__(TPB) void pra_tma_kernel(
    const float4* __restrict__ est, const float4* __restrict__ gt,
    float* __restrict__ out)
{
    __shared__ alignas(16) float4 buf_e[STAGES][F4B];
    __shared__ alignas(16) float4 buf_g[STAGES][F4B];
    __shared__ alignas(8) unsigned long long mbar_store[STAGES];

    const int tid = threadIdx.x;
    const unsigned mbar0 = (unsigned)__cvta_generic_to_shared(&mbar_store[0]);
    const size_t base = (size_t)blockIdx.x * F4B;   // tile start (float4 idx in image)

    if (tid == 0) {
        #pragma unroll
        for (int s = 0; s < STAGES; s++)
            asm volatile("mbarrier.init.shared.b64 [%0], %1;"
                         :: "r"(mbar0 + 8u * s), "r"(1) : "memory");
        asm volatile("fence.proxy.async.shared::cta;" ::: "memory");
    }
    __syncthreads();

    // Producer prologue: fill stages for b = 0,1,2
    if (tid == 0) {
        #pragma unroll
        for (int b = 0; b < STAGES - 1; b++) {
            const int s = b & (STAGES - 1);
            const unsigned mb = mbar0 + 8u * s;
            mbar_expect_tx(mb, 2 * TILE_BYTES);
            bulk_ld((unsigned)__cvta_generic_to_shared(&buf_e[s][0]),
                    &est[(size_t)b * VEC + base], TILE_BYTES, mb);
            bulk_ld((unsigned)__cvta_generic_to_shared(&buf_g[s][0]),
                    &gt [(size_t)b * VEC + base], TILE_BYTES, mb);
        }
    }

    float4 sd = make_float4(0.f, 0.f, 0.f, 0.f);  // sum_b (e - g) per lane-pixel
    float4 e2 = make_float4(0.f, 0.f, 0.f, 0.f);  // sum_b e^2 per lane-pixel
    float diff2 = 0.f;

    for (int b = 0; b < B_DIM; b++) {
        const int s = b & (STAGES - 1);
        const unsigned parity = (b >> 2) & 1;
        mbar_wait_parity(mbar0 + 8u * s, parity);

        float4 e = buf_e[s][tid];
        float4 g = buf_g[s][tid];
        float dx = e.x - g.x, dy = e.y - g.y, dz = e.z - g.z, dw = e.w - g.w;
        sd.x += dx; sd.y += dy; sd.z += dz; sd.w += dw;
        e2.x = fmaf(e.x, e.x, e2.x);
        e2.y = fmaf(e.y, e.y, e2.y);
        e2.z = fmaf(e.z, e.z, e2.z);
        e2.w = fmaf(e.w, e.w, e2.w);
        diff2 = fmaf(dx, dx, diff2);
        diff2 = fmaf(dy, dy, diff2);
        diff2 = fmaf(dz, dz, diff2);
        diff2 = fmaf(dw, dw, diff2);

        __syncthreads();   // all threads done with slot (b % STAGES)

        // Refill: stage for b+3 goes into the slot consumed at iteration b-1,
        // which is free after the barrier above.
        const int bn = b + STAGES - 1;
        if (tid == 0 && bn < B_DIM) {
            const int sn = bn & (STAGES - 1);
            const unsigned mb = mbar0 + 8u * sn;
            mbar_expect_tx(mb, 2 * TILE_BYTES);
            bulk_ld((unsigned)__cvta_generic_to_shared(&buf_e[sn][0]),
                    &est[(size_t)bn * VEC + base], TILE_BYTES, mb);
            bulk_ld((unsigned)__cvta_generic_to_shared(&buf_g[sn][0]),
                    &gt [(size_t)bn * VEC + base], TILE_BYTES, mb);
        }
    }

    float g2 = e2.x + e2.y + e2.z + e2.w;
    float h2 = (sd.x > 0.f ? e2.x : 0.f)
             + (sd.y > 0.f ? e2.y : 0.f)
             + (sd.z > 0.f ? e2.z : 0.f)
             + (sd.w > 0.f ? e2.w : 0.f);

    // ---- block reduction: warp shuffle then shared ----
    #pragma unroll
    for (int off = 16; off > 0; off >>= 1) {
        diff2 += __shfl_down_sync(0xffffffffu, diff2, off);
        g2    += __shfl_down_sync(0xffffffffu, g2,    off);
        h2    += __shfl_down_sync(0xffffffffu, h2,    off);
    }

    __shared__ float s_d[TPB / 32];
    __shared__ float s_g[TPB / 32];
    __shared__ float s_h[TPB / 32];
    const int lane = tid & 31;
    const int wid  = tid >> 5;
    if (lane == 0) { s_d[wid] = diff2; s_g[wid] = g2; s_h[wid] = h2; }
    __syncthreads();

    if (wid == 0) {
        float d  = (lane < TPB / 32) ? s_d[lane] : 0.f;
        float gg = (lane < TPB / 32) ? s_g[lane] : 0.f;
        float hh = (lane < TPB / 32) ? s_h[lane] : 0.f;
        #pragma unroll
        for (int off = 4; off > 0; off >>= 1) {
            d  += __shfl_down_sync(0xffffffffu, d,  off);
            gg += __shfl_down_sync(0xffffffffu, gg, off);
            hh += __shfl_down_sync(0xffffffffu, hh, off);
        }
        if (lane == 0) {
            atomicAdd(&g_acc[0], (double)d);
            atomicAdd(&g_acc[1], (double)gg);
            atomicAdd(&g_acc[2], (double)hh);
            __threadfence();
            unsigned int prev = atomicAdd(&g_done_count, 1u);
            if (prev == NBLOCKS - 1) {
                double diff2_t = atomicAdd(&g_acc[0], 0.0);
                double g2_t    = atomicAdd(&g_acc[1], 0.0);
                double h2_t    = atomicAdd(&g_acc[2], 0.0);
                out[0] = (float)(diff2_t / g2_t + (double)LAMBDA_F * (diff2_t / h2_t));
                g_acc[0] = 0.0;
                g_acc[1] = 0.0;
                g_acc[2] = 0.0;
                __threadfence();
                g_done_count = 0u;
            }
        }
    }
}

extern "C" void kernel_launch(void* const* d_in, const int* in_sizes, int n_in,
                              void* d_out, int out_size) {
    const float4* est = (const float4*)d_in[0];
    const float4* gt  = (const float4*)d_in[1];
    float* out = (float*)d_out;

    pra_tma_kernel<<<NBLOCKS, TPB>>>(est, gt, out);
}